// round 2
// baseline (speedup 1.0000x reference)
#include <cuda_runtime.h>
#include <cstdint>

// ConvTranspose2d(64->64, k=4, s=2, p=1) + bias + mish + (+0.5, clip[-1,1], *2)
// x: (64, 64, 64, 64) f32, w: (64, 64, 4, 4) f32, bias: (64,) f32
// out: (64, 64, 128, 128) f32
//
// Gather form: y[n,oc,oh,ow] = sum_{ic,a,b} x[n,ic,R-a,C-b] * w[oc,ic,kh(a),kw(b)]
//   R=(oh+1)>>1, C=(ow+1)>>1, ph=oh&1, pw=ow&1
//   kh: a=0 -> 1-ph, a=1 -> 3-ph ; kw: b=0 -> 1-pw, b=1 -> 3-pw
//
// Block: one (n, oh). SMEM holds rows R and R-1 for all 64 ic as overlapping
// float2 pairs Q[j] = (xv(j-1), xv(j)), j in [0,64], borders zeroed.
// Thread = (oc, pw, grp): 16 f32x2 accumulator pairs (32 pixels, stride 2 in ow).
// Hot loop per ic: 4 scalar weight LDG + 4 broadcast packs + 16*(4 LDS.64 + 4 FFMA2).

#define NIC 64
#define NOC 64
#define IH 64
#define IW 64
#define OH 128
#define OW 128
#define QROW 65                  // j = 0..64
#define Q_ELEMS (2 * NIC * QROW) // float2 entries
#define SMEM_BYTES (Q_ELEMS * 8) // 66560

__device__ __forceinline__ float postop(float y) {
    // mish(y) = y * (t^2 + 2t) / (t^2 + 2t + 2), t = e^y   (== y*tanh(softplus(y)))
    float t = __expf(fminf(y, 30.0f));
    float u = t * (t + 2.0f);
    float mish = y * __fdividef(u, u + 2.0f);
    float v = fminf(fmaxf(mish + 0.5f, -1.0f), 1.0f);
    return v * 2.0f;
}

__global__ __launch_bounds__(256)
void convt_mish_kernel(const float* __restrict__ x,
                       const float* __restrict__ weight,
                       const float* __restrict__ bias,
                       float* __restrict__ out) {
    extern __shared__ char smem_raw[];
    const int tid = threadIdx.x;
    const int oh  = blockIdx.x;   // 0..127
    const int n   = blockIdx.y;   // 0..63

    const int ph = oh & 1;
    const int R  = (oh + 1) >> 1;   // 0..64

    // ---------------- stage input pair-rows into SMEM ----------------
    {
        float2* Qf = (float2*)smem_raw;
        for (int i = tid; i < Q_ELEMS; i += 256) {
            int a   = i / (NIC * QROW);          // 0: row R, 1: row R-1
            int rem = i - a * (NIC * QROW);
            int ic  = rem / QROW;
            int j   = rem - ic * QROW;           // 0..64
            int r   = R - a;
            float v0 = 0.0f, v1 = 0.0f;
            if (r >= 0 && r < IH) {
                const float* xr = x + (((size_t)n * NIC + ic) * IH + r) * IW;
                if (j >= 1)  v0 = xr[j - 1];
                if (j <= 63) v1 = xr[j];
            }
            Qf[i] = make_float2(v0, v1);
        }
    }
    __syncthreads();

    // ---------------- compute ----------------
    const int oc  = tid & 63;
    const int pw  = (tid >> 6) & 1;
    const int grp = tid >> 7;          // 0,1

    const int kh0 = 1 - ph, kh1 = 3 - ph;
    const int kw0 = 1 - pw, kw1 = 3 - pw;
    const int wi00 = (kh0 << 2) + kw0;
    const int wi01 = (kh0 << 2) + kw1;
    const int wi10 = (kh1 << 2) + kw0;
    const int wi11 = (kh1 << 2) + kw1;

    const float* wbase = weight + oc * (NIC * 16);

    unsigned long long acc[16];
#pragma unroll
    for (int p = 0; p < 16; p++) acc[p] = 0ull;

    const int jbase = 32 * grp + pw;   // Q index of pair-local p=0, b=1 operand
    const unsigned long long* Qull = (const unsigned long long*)smem_raw;

#pragma unroll 1
    for (int ic = 0; ic < NIC; ic++) {
        const float* wp = wbase + ic * 16;
        float w00 = __ldg(wp + wi00);
        float w01 = __ldg(wp + wi01);
        float w10 = __ldg(wp + wi10);
        float w11 = __ldg(wp + wi11);
        unsigned long long W00, W01, W10, W11;
        asm("mov.b64 %0, {%1, %1};" : "=l"(W00) : "r"(__float_as_uint(w00)));
        asm("mov.b64 %0, {%1, %1};" : "=l"(W01) : "r"(__float_as_uint(w01)));
        asm("mov.b64 %0, {%1, %1};" : "=l"(W10) : "r"(__float_as_uint(w10)));
        asm("mov.b64 %0, {%1, %1};" : "=l"(W11) : "r"(__float_as_uint(w11)));

        const unsigned long long* rA = Qull + ic * QROW + jbase;          // row R   (a=0)
        const unsigned long long* rB = Qull + (NIC + ic) * QROW + jbase;  // row R-1 (a=1)

#pragma unroll
        for (int p = 0; p < 16; p++) {
            unsigned long long a1 = rA[2 * p];       // b=1 operand (iw = C-1)
            unsigned long long a0 = rA[2 * p + 1];   // b=0 operand (iw = C)
            unsigned long long b1 = rB[2 * p];
            unsigned long long b0 = rB[2 * p + 1];
            asm("fma.rn.f32x2 %0, %1, %2, %0;" : "+l"(acc[p]) : "l"(a0), "l"(W00));
            asm("fma.rn.f32x2 %0, %1, %2, %0;" : "+l"(acc[p]) : "l"(a1), "l"(W01));
            asm("fma.rn.f32x2 %0, %1, %2, %0;" : "+l"(acc[p]) : "l"(b0), "l"(W10));
            asm("fma.rn.f32x2 %0, %1, %2, %0;" : "+l"(acc[p]) : "l"(b1), "l"(W11));
        }
    }

    // ---------------- epilogue: postop into padded SMEM, then coalesced store ----------------
    __syncthreads();   // done reading Q; reuse buffer
    float* ys = (float*)smem_raw;      // [64][129] padded
    const float bz = __ldg(bias + oc);

#pragma unroll
    for (int p = 0; p < 16; p++) {
        float lo = __uint_as_float((unsigned)(acc[p] & 0xffffffffull));
        float hi = __uint_as_float((unsigned)(acc[p] >> 32));
        int m0  = 2 * (16 * grp + p);      // pixel index within pw class
        int ow0 = pw + 2 * m0;
        ys[oc * 129 + ow0]     = postop(lo + bz);
        ys[oc * 129 + ow0 + 2] = postop(hi + bz);
    }
    __syncthreads();

    for (int i = tid; i < NOC * OW; i += 256) {
        int oco = i >> 7;
        int ow  = i & 127;
        out[(((size_t)n * NOC + oco) * OH + oh) * OW + ow] = ys[oco * 129 + ow];
    }
}

extern "C" void kernel_launch(void* const* d_in, const int* in_sizes, int n_in,
                              void* d_out, int out_size) {
    const float* x      = (const float*)d_in[0];
    const float* weight = (const float*)d_in[1];
    const float* bias   = (const float*)d_in[2];
    float* out          = (float*)d_out;

    cudaFuncSetAttribute(convt_mish_kernel,
                         cudaFuncAttributeMaxDynamicSharedMemorySize, SMEM_BYTES);
    dim3 grid(OH, 64);   // (oh, n)
    convt_mish_kernel<<<grid, 256, SMEM_BYTES>>>(x, weight, bias, out);
}

// round 3
// speedup vs baseline: 1.9134x; 1.9134x over previous
#include <cuda_runtime.h>
#include <cstdint>

// ConvTranspose2d(64->64, k=4, s=2, p=1) + bias + mish + (+0.5, clip, *2)
// x: (64,64,64,64) f32, w: (64,64,4,4), bias: (64,), out: (64,64,128,128)
//
// Gather form per output (n,oc,oh,ow):
//   R=(oh+1)>>1, ph=oh&1, pw=ow&1, m=(ow-pw)/2, C=m+pw
//   y = sum_ic sum_{a,b in {0,1}} x[n,ic,R-a,C-b] * w[oc,ic,kh_a,kw_b]
//   kh_a = (a? 3-ph : 1-ph), kw_b = (b? 3-pw : 1-pw)
//
// f32x2 packs TWO OUTPUT CHANNELS (2k,2k+1): weight operand is adjacent-oc u64
// straight from SMEM (no packing); input operand is (x,x) pre-duplicated in SMEM.
// Block = (n, oh): 256 threads, thread = 8 oc-pairs x 2 pixels, one pw.
// Hot loop/ic/thread: 6 LDS.64 (input) + 16 warp-uniform LDS.128 (weights) + 64 FFMA2.

#define ICN 64
#define OCN 64
#define IH 64
#define IW 64
#define OHT 128
#define OWD 128

// SMEM u64 layout:
//   D[s][arr][ic][34] : input, s=0 row R-1, s=1 row R; arr = d&1 (even/odd d), idx=d>>1
//     d in [0,65], value = x[.., d-1] duplicated (x,x); OOB -> 0
//   sizes: arr stride 64*34=2176, s stride 4352, total 8704 u64 (69632 B)
//   W[pw][ic][opair(32)][tap(4)] : (w[2op][tap], w[2op+1][tap]); 16384 u64 (131072 B)
#define D_ARR_STRIDE 2176
#define D_S_STRIDE   4352
#define D_IC_STRIDE  34
#define D_U64        8704
#define W_U64        16384
#define SMEM_BYTES   ((D_U64 + W_U64) * 8)   // 200704

__device__ __forceinline__ unsigned long long pack2(float a, float b) {
    unsigned long long r;
    asm("mov.b64 %0, {%1, %2};" : "=l"(r) : "r"(__float_as_uint(a)), "r"(__float_as_uint(b)));
    return r;
}

__device__ __forceinline__ void ffma2(unsigned long long& acc,
                                      unsigned long long a, unsigned long long w) {
    asm("fma.rn.f32x2 %0, %1, %2, %0;" : "+l"(acc) : "l"(a), "l"(w));
}

__device__ __forceinline__ float postop(float y) {
    // mish(y) = y*(t^2+2t)/(t^2+2t+2), t=e^y
    float t = __expf(fminf(y, 30.0f));
    float u = t * (t + 2.0f);
    float mish = y * __fdividef(u, u + 2.0f);
    float v = fminf(fmaxf(mish + 0.5f, -1.0f), 1.0f);
    return v * 2.0f;
}

__global__ __launch_bounds__(256, 1)
void convt_mish_kernel(const float* __restrict__ x,
                       const float* __restrict__ weight,
                       const float* __restrict__ bias,
                       float* __restrict__ out) {
    extern __shared__ unsigned long long sm[];
    unsigned long long* Dm = sm;
    unsigned long long* Wm = sm + D_U64;

    const int tid = threadIdx.x;
    const int oh  = blockIdx.x;
    const int n   = blockIdx.y;
    const int ph  = oh & 1;
    const int R   = (oh + 1) >> 1;          // rows used: R (s=1), R-1 (s=0)

    // -------- stage inputs: D[s][d&1][ic][d>>1] = (xv, xv), xv = x[n,ic,R-1+s,d-1] --------
    for (int i = tid; i < 2 * ICN * 66; i += 256) {
        int s   = i / (ICN * 66);
        int rem = i - s * (ICN * 66);
        int ic  = rem / 66;
        int d   = rem - ic * 66;
        int r   = R - 1 + s;
        int j   = d - 1;
        float v = 0.0f;
        if (r >= 0 && r < IH && j >= 0 && j < IW)
            v = x[(((size_t)n * ICN + ic) * IH + r) * IW + j];
        Dm[(s * 2 + (d & 1)) * D_ARR_STRIDE + ic * D_IC_STRIDE + (d >> 1)] = pack2(v, v);
    }

    // -------- stage weights: Wm[((pw*64+ic)*32+op)*4 + t] = (w[2op][..], w[2op+1][..]) ----
    for (int i = tid; i < W_U64; i += 256) {
        int t   = i & 3;
        int op  = (i >> 2) & 31;
        int ic  = (i >> 7) & 63;
        int pw  = i >> 13;
        int kh  = (t & 2) ? (3 - ph) : (1 - ph);
        int kw  = (t & 1) ? (3 - pw) : (1 - pw);
        int oc0 = 2 * op;
        float f0 = __ldg(weight + (((oc0    ) * ICN + ic) << 4) + (kh << 2) + kw);
        float f1 = __ldg(weight + (((oc0 + 1) * ICN + ic) << 4) + (kh << 2) + kw);
        Wm[i] = pack2(f0, f1);
    }
    __syncthreads();

    // -------- compute --------
    // warp = tid>>5: og = warp&3 (oc-pairs 8og..8og+7), pw = warp>>2. lane = pixg (0..31).
    const int pixg = tid & 31;
    const int og   = (tid >> 5) & 3;
    const int pw   = tid >> 7;

    // pixels m0=2*pixg, m0+1 ; d0 = 2*pixg + pw
    const int d0 = 2 * pixg + pw;
    int o0 = (d0 & 1) * D_ARR_STRIDE + (d0 >> 1);
    int o1 = ((d0 + 1) & 1) * D_ARR_STRIDE + ((d0 + 1) >> 1);
    int o2 = ((d0 + 2) & 1) * D_ARR_STRIDE + ((d0 + 2) >> 1);

    unsigned long long acc[8][2];
#pragma unroll
    for (int op = 0; op < 8; op++) { acc[op][0] = 0ull; acc[op][1] = 0ull; }

    const unsigned long long* wbase0 = Wm + ((size_t)pw * ICN) * 32 * 4 + 8 * og * 4;

#pragma unroll 2
    for (int ic = 0; ic < ICN; ic++) {
        const int db = ic * D_IC_STRIDE;
        unsigned long long B0 = Dm[db + o0];                 // row R-1
        unsigned long long B1 = Dm[db + o1];
        unsigned long long B2 = Dm[db + o2];
        unsigned long long A0 = Dm[D_S_STRIDE + db + o0];    // row R
        unsigned long long A1 = Dm[D_S_STRIDE + db + o1];
        unsigned long long A2 = Dm[D_S_STRIDE + db + o2];

        const unsigned long long* wb = wbase0 + ic * 128;    // 32*4 per ic
#pragma unroll
        for (int op = 0; op < 8; op++) {
            ulonglong2 wa = *(const ulonglong2*)(wb + op * 4);      // t0 (W00), t1 (W01)
            ulonglong2 wc = *(const ulonglong2*)(wb + op * 4 + 2);  // t2 (W10), t3 (W11)
            ffma2(acc[op][0], A1, wa.x);   // pixel m0:   a=0,b=0
            ffma2(acc[op][0], A0, wa.y);   //             a=0,b=1
            ffma2(acc[op][0], B1, wc.x);   //             a=1,b=0
            ffma2(acc[op][0], B0, wc.y);   //             a=1,b=1
            ffma2(acc[op][1], A2, wa.x);   // pixel m0+1
            ffma2(acc[op][1], A1, wa.y);
            ffma2(acc[op][1], B2, wc.x);
            ffma2(acc[op][1], B1, wc.y);
        }
    }

    // -------- epilogue: postop -> padded SMEM (reuse D region) -> coalesced store --------
    __syncthreads();
    float* ys = (float*)sm;             // [64][129], 33 KB < D region
#pragma unroll
    for (int op = 0; op < 8; op++) {
        int oc0 = 16 * og + 2 * op;
        float bz0 = __ldg(bias + oc0);
        float bz1 = __ldg(bias + oc0 + 1);
#pragma unroll
        for (int px = 0; px < 2; px++) {
            int ow = pw + 4 * pixg + 2 * px;
            unsigned long long a = acc[op][px];
            float lo = __uint_as_float((unsigned)(a & 0xffffffffull));
            float hi = __uint_as_float((unsigned)(a >> 32));
            ys[oc0 * 129 + ow]       = postop(lo + bz0);
            ys[(oc0 + 1) * 129 + ow] = postop(hi + bz1);
        }
    }
    __syncthreads();

    for (int i = tid; i < OCN * OWD; i += 256) {
        int oc = i >> 7;
        int ow = i & 127;
        out[(((size_t)n * OCN + oc) * OHT + oh) * OWD + ow] = ys[oc * 129 + ow];
    }
}

extern "C" void kernel_launch(void* const* d_in, const int* in_sizes, int n_in,
                              void* d_out, int out_size) {
    const float* x      = (const float*)d_in[0];
    const float* weight = (const float*)d_in[1];
    const float* bias   = (const float*)d_in[2];
    float* out          = (float*)d_out;

    cudaFuncSetAttribute(convt_mish_kernel,
                         cudaFuncAttributeMaxDynamicSharedMemorySize, SMEM_BYTES);
    dim3 grid(OHT, 64);
    convt_mish_kernel<<<grid, 256, SMEM_BYTES>>>(x, weight, bias, out);
}

// round 5
// speedup vs baseline: 2.8708x; 1.5004x over previous
#include <cuda_runtime.h>
#include <cstdint>

// ConvTranspose2d(64->64,k4,s2,p1)+bias+mish+(+0.5,clip,*2) via mma.sync tf32.
// y[p,oc] = sum_k A[p,k]*B[oc,k], k = (b*2+a)*64 + ic, K=256.
//   pixel p=(ohi,m): oh = ph+4t+2*ohi, ow = 2m+pw ; Rb = 2t+ph
//   A[p,k] = x[n, ic, Rb+ohi-a, m+pw-b]   (zero OOB)
//   B[oc,k] = w[oc, ic, (1-ph)+2a, (1-pw)+2b]
// xT[r(3)][c(66)][ic(64)] tf32, ic contiguous (stride 68) -> ldmatrix reads A
// fragments DIRECTLY from xT (no im2col). B staged once per CTA (ph fixed).
// Persistent: 148 CTAs (74 per ph), 2048 tiles (n,t) per ph.

#define ICS 68                      // xT ic stride (floats); 272B rows: LDSM conflict-free
#define SM_BIAS 0
#define SM_B    1024
#define B_PW_BYTES 65536
#define SM_U    (SM_B + 2 * B_PW_BYTES)   // 132096: union of xT (53856B) / ys (67584B)
#define YS_PW_W (64 * 132)
#define SMEM_TOTAL (SM_U + 2 * YS_PW_W * 4)   // 199680

static __device__ __forceinline__ uint32_t s2u(const void* p) {
    uint32_t a;
    asm("{ .reg .u64 t; cvta.to.shared.u64 t, %1; cvt.u32.u64 %0, t; }" : "=r"(a) : "l"(p));
    return a;
}
static __device__ __forceinline__ uint32_t cvt_tf32(float f) {
    uint32_t r; asm("cvt.rn.tf32.f32 %0, %1;" : "=r"(r) : "f"(f)); return r;
}
static __device__ __forceinline__ void sts32(uint32_t addr, uint32_t v) {
    asm volatile("st.shared.b32 [%0], %1;" :: "r"(addr), "r"(v) : "memory");
}
static __device__ __forceinline__ void ldsm4(uint32_t* r, uint32_t addr) {
    asm volatile("ldmatrix.sync.aligned.m8n8.x4.shared.b16 {%0,%1,%2,%3}, [%4];"
                 : "=r"(r[0]), "=r"(r[1]), "=r"(r[2]), "=r"(r[3]) : "r"(addr));
}
static __device__ __forceinline__ void mma8(float* d, const uint32_t* a,
                                            uint32_t b0, uint32_t b1) {
    asm volatile("mma.sync.aligned.m16n8k8.row.col.f32.tf32.tf32.f32 "
                 "{%0,%1,%2,%3}, {%4,%5,%6,%7}, {%8,%9}, {%0,%1,%2,%3};"
                 : "+f"(d[0]), "+f"(d[1]), "+f"(d[2]), "+f"(d[3])
                 : "r"(a[0]), "r"(a[1]), "r"(a[2]), "r"(a[3]), "r"(b0), "r"(b1));
}

__device__ __forceinline__ float postop(float y) {
    // mish(y) = y*(t^2+2t)/(t^2+2t+2), t=e^y ; then +0.5, clip[-1,1], *2
    float t = __expf(fminf(y, 30.0f));
    float u = t * (t + 2.0f);
    float mish = y * __fdividef(u, u + 2.0f);
    float v = fminf(fmaxf(mish + 0.5f, -1.0f), 1.0f);
    return v * 2.0f;
}

__global__ __launch_bounds__(256, 1)
void convt_mma_kernel(const float* __restrict__ x,
                      const float* __restrict__ weight,
                      const float* __restrict__ bias,
                      float* __restrict__ out) {
    extern __shared__ char smem[];
    const uint32_t sb = s2u(smem);
    const int tid  = threadIdx.x;
    const int warp = tid >> 5;
    const int lane = tid & 31;
    const int ph   = blockIdx.x & 1;
    const int slot = blockIdx.x >> 1;   // 0..73

    if (tid < 64) ((float*)smem)[tid] = bias[tid];

    // ---- stage B once: B[pw][oc][k] tf32, row 1024B, byte = k*4 ^ ((oc&7)<<4) ----
    for (int it = 0; it < 128; it++) {
        int idx = tid + it * 256;          // 0..32767
        int pw = idx >> 14;
        int oc = (idx >> 8) & 63;
        int k  = idx & 255;
        int g = k >> 6, ic = k & 63, a = g & 1, b = g >> 1;
        int kh = (1 - ph) + 2 * a;
        int kw = (1 - pw) + 2 * b;
        float f = __ldg(weight + ((oc * 64 + ic) << 4) + (kh << 2) + kw);
        uint32_t byte = ((uint32_t)(k << 2)) ^ ((uint32_t)(oc & 7) << 4);
        sts32(sb + SM_B + pw * B_PW_BYTES + oc * 1024 + byte, cvt_tf32(f));
    }
    __syncthreads();

    // warp roles
    const int pw  = warp >> 2;
    const int mq  = warp & 3;
    const int p0  = 32 * mq;               // pixel base (p = ohi*64 + m)
    const int ohi = mq >> 1;
    const int msub0 = 32 * (mq & 1);

    // per-lane LDSM indices
    const int l15 = lane & 15;
    const int lhi = lane >> 4;
    const int oc_l = (lane & 7) + 8 * lhi;
    const uint32_t khalf = (uint32_t)((lane >> 3) & 1) << 4;   // 0 or 16
    const uint32_t swzB  = (uint32_t)(lane & 7) << 4;
    uint32_t rbB[4];
#pragma unroll
    for (int jp = 0; jp < 4; jp++)
        rbB[jp] = sb + SM_B + pw * B_PW_BYTES + (16 * jp + oc_l) * 1024;

    for (int widx = slot; widx < 2048; widx += 74) {
        const int n = widx >> 5;
        const int t = widx & 31;
        const int Rb = 2 * t + ph;
        const float* xn = x + (size_t)n * (64 * 64 * 64);

        // ---- stage xT[r][c][ic] (tf32), zero borders: r = Rb-1..Rb+1, c-1 = j ----
        for (int it = 0; it < 50; it++) {
            int idx = tid + it * 256;
            if (idx < 12672) {                   // 192 * 66
                int rr = idx / 66;
                int c  = idx - rr * 66;
                int r  = rr >> 6;                // 0..2
                int ic = rr & 63;
                int rg = Rb - 1 + r;
                int j  = c - 1;
                float v = 0.0f;
                if ((unsigned)rg < 64u && (unsigned)j < 64u)
                    v = __ldg(xn + (ic * 64 + rg) * 64 + j);
                sts32(sb + SM_U + (((r * 66 + c) * ICS + ic) << 2), cvt_tf32(v));
            }
        }
        __syncthreads();

        float acc[2][8][4];
#pragma unroll
        for (int i = 0; i < 2; i++)
#pragma unroll
            for (int j = 0; j < 8; j++)
#pragma unroll
                for (int e = 0; e < 4; e++) acc[i][j][e] = 0.0f;

#pragma unroll
        for (int g = 0; g < 4; g++) {
            const int a = g & 1, b = g >> 1;
            const int rowsel  = ohi + 1 - a;
            const int colbase = msub0 + pw - b + 1;
            uint32_t aA0 = sb + SM_U + (uint32_t)(((rowsel * 66 + colbase + l15) * ICS) << 2)
                         + ((uint32_t)lhi << 4);
            uint32_t aA1 = aA0 + ((16 * ICS) << 2);
            const uint32_t kb0 = (uint32_t)(g << 8) + khalf;   // logical byte in B row

#pragma unroll
            for (int s8 = 0; s8 < 8; s8++) {
                uint32_t Af0[4], Af1[4];
                ldsm4(Af0, aA0);
                ldsm4(Af1, aA1);
                const uint32_t kb = kb0 + (uint32_t)(s8 << 5);
                uint32_t Bf[4][4];
#pragma unroll
                for (int jp = 0; jp < 4; jp++)
                    ldsm4(Bf[jp], rbB[jp] + (kb ^ swzB));
#pragma unroll
                for (int jp = 0; jp < 4; jp++) {
                    mma8(acc[0][2 * jp],     Af0, Bf[jp][0], Bf[jp][1]);
                    mma8(acc[0][2 * jp + 1], Af0, Bf[jp][2], Bf[jp][3]);
                    mma8(acc[1][2 * jp],     Af1, Bf[jp][0], Bf[jp][1]);
                    mma8(acc[1][2 * jp + 1], Af1, Bf[jp][2], Bf[jp][3]);
                }
                aA0 += 32;
                aA1 += 32;
            }
        }
        __syncthreads();   // xT dead; region becomes ys

        // ---- epilogue: postop -> ys[pw][oc][132-padded p] ----
        float* ysf = (float*)(smem + SM_U);
        const float* bsm = (const float*)smem;
        const int gL = lane >> 2, tg = lane & 3;
#pragma unroll
        for (int i = 0; i < 2; i++) {
            const int prow = p0 + 16 * i + gL;
#pragma unroll
            for (int j = 0; j < 8; j++) {
                const int oc = 8 * j + 2 * tg;
                const float b0v = bsm[oc], b1v = bsm[oc + 1];
                const int base = pw * YS_PW_W + oc * 132;
                ysf[base + prow]           = postop(acc[i][j][0] + b0v);
                ysf[base + 132 + prow]     = postop(acc[i][j][1] + b1v);
                ysf[base + prow + 8]       = postop(acc[i][j][2] + b0v);
                ysf[base + 132 + prow + 8] = postop(acc[i][j][3] + b1v);
            }
        }
        __syncthreads();

        // ---- coalesced store: 4096 float4 ----
        for (int it = 0; it < 16; it++) {
            int vid = tid + it * 256;
            int ow4 = vid & 31;
            int row = vid >> 5;            // 0..127
            int oh2 = row & 1;
            int oc  = row >> 1;
            int m0  = 2 * ow4;
            int pb  = oh2 * 64;
            float4 v;
            v.x = ysf[0 * YS_PW_W + oc * 132 + pb + m0];
            v.y = ysf[1 * YS_PW_W + oc * 132 + pb + m0];
            v.z = ysf[0 * YS_PW_W + oc * 132 + pb + m0 + 1];
            v.w = ysf[1 * YS_PW_W + oc * 132 + pb + m0 + 1];
            int oh = ph + 4 * t + 2 * oh2;
            *(float4*)(out + (((size_t)n * 64 + oc) * 128 + oh) * 128 + 4 * ow4) = v;
        }
        __syncthreads();   // ys dead before next tile's xT staging
    }
}

extern "C" void kernel_launch(void* const* d_in, const int* in_sizes, int n_in,
                              void* d_out, int out_size) {
    const float* x      = (const float*)d_in[0];
    const float* weight = (const float*)d_in[1];
    const float* bias   = (const float*)d_in[2];
    float* out          = (float*)d_out;

    cudaFuncSetAttribute(convt_mma_kernel,
                         cudaFuncAttributeMaxDynamicSharedMemorySize, SMEM_TOTAL);
    convt_mma_kernel<<<148, 256, SMEM_TOTAL>>>(x, weight, bias, out);
}

// round 6
// speedup vs baseline: 5.5535x; 1.9345x over previous
#include <cuda_runtime.h>
#include <cstdint>

// ConvTranspose2d(64->64,k4,s2,p1)+bias+mish+(+0.5,clip,*2) via mma.sync tf32.
// y[p,oc] = sum_k A[p,k]*B[oc,k], k = (b*2+a)*64 + ic, K=256.
//   pixel p=(ohi,m): oh = ph+4t+2*ohi, ow = 2m+pw ; Rb = 2t+ph
//   A[p,k] = x[n, ic, Rb+ohi-a, m+pw-b]   (zero OOB)
//   B[oc,k] = w[oc, ic, (1-ph)+2a, (1-pw)+2b]
// xT[r(3)][c(66)][ic(64)] tf32, ic contiguous (stride 68) -> ldmatrix reads A
// fragments DIRECTLY from xT (no im2col). B staged once per CTA (ph fixed).
// 512 threads, 16 warps: warp = (pw, och, mq), warp tile 32px x 32oc (32 acc regs).
// Persistent: 148 CTAs (74 per ph), 2048 tiles (n,t) per ph.

#define NT 512
#define ICS 68                      // xT ic stride (floats); 272B rows: LDSM conflict-free
#define SM_B    1024
#define B_PW_BYTES 65536
#define SM_U    (SM_B + 2 * B_PW_BYTES)   // 132096: union of xT (53856B) / ys (67584B)
#define YS_PW_W (64 * 132)
#define SMEM_TOTAL (SM_U + 2 * YS_PW_W * 4)   // 199680

static __device__ __forceinline__ uint32_t s2u(const void* p) {
    uint32_t a;
    asm("{ .reg .u64 t; cvta.to.shared.u64 t, %1; cvt.u32.u64 %0, t; }" : "=r"(a) : "l"(p));
    return a;
}
static __device__ __forceinline__ uint32_t cvt_tf32(float f) {
    uint32_t r; asm("cvt.rn.tf32.f32 %0, %1;" : "=r"(r) : "f"(f)); return r;
}
static __device__ __forceinline__ void sts32(uint32_t addr, uint32_t v) {
    asm volatile("st.shared.b32 [%0], %1;" :: "r"(addr), "r"(v) : "memory");
}
static __device__ __forceinline__ void ldsm4(uint32_t* r, uint32_t addr) {
    asm volatile("ldmatrix.sync.aligned.m8n8.x4.shared.b16 {%0,%1,%2,%3}, [%4];"
                 : "=r"(r[0]), "=r"(r[1]), "=r"(r[2]), "=r"(r[3]) : "r"(addr));
}
static __device__ __forceinline__ void mma8(float* d, const uint32_t* a,
                                            uint32_t b0, uint32_t b1) {
    asm volatile("mma.sync.aligned.m16n8k8.row.col.f32.tf32.tf32.f32 "
                 "{%0,%1,%2,%3}, {%4,%5,%6,%7}, {%8,%9}, {%0,%1,%2,%3};"
                 : "+f"(d[0]), "+f"(d[1]), "+f"(d[2]), "+f"(d[3])
                 : "r"(a[0]), "r"(a[1]), "r"(a[2]), "r"(a[3]), "r"(b0), "r"(b1));
}

__device__ __forceinline__ float postop(float y) {
    // mish(y) = y*(t^2+2t)/(t^2+2t+2), t=e^y ; then +0.5, clip[-1,1], *2
    float t = __expf(fminf(y, 30.0f));
    float u = t * (t + 2.0f);
    float mish = y * __fdividef(u, u + 2.0f);
    float v = fminf(fmaxf(mish + 0.5f, -1.0f), 1.0f);
    return v * 2.0f;
}

__global__ __launch_bounds__(NT, 1)
void convt_mma_kernel(const float* __restrict__ x,
                      const float* __restrict__ weight,
                      const float* __restrict__ bias,
                      float* __restrict__ out) {
    extern __shared__ char smem[];
    const uint32_t sb = s2u(smem);
    const int tid  = threadIdx.x;
    const int warp = tid >> 5;
    const int lane = tid & 31;
    const int ph   = blockIdx.x & 1;
    const int slot = blockIdx.x >> 1;   // 0..73

    if (tid < 64) ((float*)smem)[tid] = bias[tid];

    // ---- stage B once: B[pw][oc][k] tf32, row 1024B, byte = k*4 ^ ((oc&7)<<4) ----
    for (int it = 0; it < 64; it++) {
        int idx = tid + it * NT;           // 0..32767
        int pw = idx >> 14;
        int oc = (idx >> 8) & 63;
        int k  = idx & 255;
        int g = k >> 6, ic = k & 63, a = g & 1, b = g >> 1;
        int kh = (1 - ph) + 2 * a;
        int kw = (1 - pw) + 2 * b;
        float f = __ldg(weight + ((oc * 64 + ic) << 4) + (kh << 2) + kw);
        uint32_t byte = ((uint32_t)(k << 2)) ^ ((uint32_t)(oc & 7) << 4);
        sts32(sb + SM_B + pw * B_PW_BYTES + oc * 1024 + byte, cvt_tf32(f));
    }
    __syncthreads();

    // warp roles: pw | och | mq
    const int pw  = warp >> 3;
    const int och = (warp >> 2) & 1;
    const int mq  = warp & 3;
    const int p0  = 32 * mq;               // pixel base (p = ohi*64 + m)
    const int ohi = mq >> 1;
    const int msub0 = 32 * (mq & 1);

    // per-lane LDSM indices
    const int l15 = lane & 15;
    const int lhi = lane >> 4;
    const int oc_l = (lane & 7) + 8 * lhi;
    const uint32_t khalf = (uint32_t)((lane >> 3) & 1) << 4;   // 0 or 16
    const uint32_t swzB  = (uint32_t)(lane & 7) << 4;
    uint32_t rbB[2];
#pragma unroll
    for (int jp = 0; jp < 2; jp++)
        rbB[jp] = sb + SM_B + pw * B_PW_BYTES + (32 * och + 16 * jp + oc_l) * 1024;

    for (int widx = slot; widx < 2048; widx += 74) {
        const int n = widx >> 5;
        const int t = widx & 31;
        const int Rb = 2 * t + ph;
        const float* xn = x + (size_t)n * (64 * 64 * 64);

        // ---- stage xT[r][c][ic] (tf32), zero borders: r = Rb-1..Rb+1, c-1 = j ----
        for (int it = 0; it < 25; it++) {
            int idx = tid + it * NT;
            if (idx < 12672) {                   // 192 * 66
                int rr = idx / 66;
                int c  = idx - rr * 66;
                int r  = rr >> 6;                // 0..2
                int ic = rr & 63;
                int rg = Rb - 1 + r;
                int j  = c - 1;
                float v = 0.0f;
                if ((unsigned)rg < 64u && (unsigned)j < 64u)
                    v = __ldg(xn + (ic * 64 + rg) * 64 + j);
                sts32(sb + SM_U + (((r * 66 + c) * ICS + ic) << 2), cvt_tf32(v));
            }
        }
        __syncthreads();

        float acc[2][4][4];
#pragma unroll
        for (int i = 0; i < 2; i++)
#pragma unroll
            for (int j = 0; j < 4; j++)
#pragma unroll
                for (int e = 0; e < 4; e++) acc[i][j][e] = 0.0f;

#pragma unroll
        for (int g = 0; g < 4; g++) {
            const int a = g & 1, b = g >> 1;
            const int rowsel  = ohi + 1 - a;
            const int colbase = msub0 + pw - b + 1;
            uint32_t aA0 = sb + SM_U + (uint32_t)(((rowsel * 66 + colbase + l15) * ICS) << 2)
                         + ((uint32_t)lhi << 4);
            uint32_t aA1 = aA0 + ((16 * ICS) << 2);
            const uint32_t kb0 = (uint32_t)(g << 8) + khalf;   // logical byte in B row

#pragma unroll
            for (int s8 = 0; s8 < 8; s8++) {
                uint32_t Af0[4], Af1[4];
                ldsm4(Af0, aA0);
                ldsm4(Af1, aA1);
                const uint32_t kb = (kb0 + (uint32_t)(s8 << 5)) ^ swzB;
                uint32_t Bf[2][4];
                ldsm4(Bf[0], rbB[0] + kb);
                ldsm4(Bf[1], rbB[1] + kb);
#pragma unroll
                for (int jp = 0; jp < 2; jp++) {
                    mma8(acc[0][2 * jp],     Af0, Bf[jp][0], Bf[jp][1]);
                    mma8(acc[0][2 * jp + 1], Af0, Bf[jp][2], Bf[jp][3]);
                    mma8(acc[1][2 * jp],     Af1, Bf[jp][0], Bf[jp][1]);
                    mma8(acc[1][2 * jp + 1], Af1, Bf[jp][2], Bf[jp][3]);
                }
                aA0 += 32;
                aA1 += 32;
            }
        }
        __syncthreads();   // xT dead; region becomes ys

        // ---- epilogue: postop -> ys[pw][oc][132-padded p] ----
        float* ysf = (float*)(smem + SM_U);
        const float* bsm = (const float*)smem;
        const int gL = lane >> 2, tg = lane & 3;
#pragma unroll
        for (int i = 0; i < 2; i++) {
            const int prow = p0 + 16 * i + gL;
#pragma unroll
            for (int j = 0; j < 4; j++) {
                const int oc = 32 * och + 8 * j + 2 * tg;
                const float b0v = bsm[oc], b1v = bsm[oc + 1];
                const int base = pw * YS_PW_W + oc * 132;
                ysf[base + prow]           = postop(acc[i][j][0] + b0v);
                ysf[base + 132 + prow]     = postop(acc[i][j][1] + b1v);
                ysf[base + prow + 8]       = postop(acc[i][j][2] + b0v);
                ysf[base + 132 + prow + 8] = postop(acc[i][j][3] + b1v);
            }
        }
        __syncthreads();

        // ---- coalesced store: 4096 float4 ----
        for (int it = 0; it < 8; it++) {
            int vid = tid + it * NT;
            int ow4 = vid & 31;
            int row = vid >> 5;            // 0..127
            int oh2 = row & 1;
            int oc  = row >> 1;
            int m0  = 2 * ow4;
            int pb  = oh2 * 64;
            float4 v;
            v.x = ysf[0 * YS_PW_W + oc * 132 + pb + m0];
            v.y = ysf[1 * YS_PW_W + oc * 132 + pb + m0];
            v.z = ysf[0 * YS_PW_W + oc * 132 + pb + m0 + 1];
            v.w = ysf[1 * YS_PW_W + oc * 132 + pb + m0 + 1];
            int oh = ph + 4 * t + 2 * oh2;
            *(float4*)(out + (((size_t)n * 64 + oc) * 128 + oh) * 128 + 4 * ow4) = v;
        }
        __syncthreads();   // ys dead before next tile's xT staging
    }
}

extern "C" void kernel_launch(void* const* d_in, const int* in_sizes, int n_in,
                              void* d_out, int out_size) {
    const float* x      = (const float*)d_in[0];
    const float* weight = (const float*)d_in[1];
    const float* bias   = (const float*)d_in[2];
    float* out          = (float*)d_out;

    cudaFuncSetAttribute(convt_mma_kernel,
                         cudaFuncAttributeMaxDynamicSharedMemorySize, SMEM_TOTAL);
    convt_mma_kernel<<<148, NT, SMEM_TOTAL>>>(x, weight, bias, out);
}